// round 1
// baseline (speedup 1.0000x reference)
#include <cuda_runtime.h>

#define G   16
#define Bsz 2
#define C   256
#define Cg  16
#define HW  576     // 24*24
#define AC  6400    // 25*C
#define EPSI 1e-5f

// Scratch (device globals — no allocation allowed)
__device__ float g_h1[G*Bsz*C*HW];     // (i,b,c,hw)  18.9 MB
__device__ float g_pooled[G*Bsz*AC];   // (i,b,ac)
__device__ float g_aff[G*Bsz*G];       // aff_i[i,b,l]

// ---------------------------------------------------------------------------
// Kernel 1: 16x grouped 3x3 conv + BN + ReLU  ->  g_h1
// Block = (i, b, group k). 192 threads, each owns 3 pixels x 16 out-channels.
// x tile (16ch x 576) + weights (16oc x 16cin x 9) in smem. Borders via
// predicated LDS (no padded tile -> stays under 48KB static smem).
// ---------------------------------------------------------------------------
__global__ __launch_bounds__(192) void conv1_kernel(
    const float* __restrict__ x,  const float* __restrict__ W1,
    const float* __restrict__ g1, const float* __restrict__ b1,
    const float* __restrict__ m1, const float* __restrict__ v1)
{
    __shared__ float tile[16*HW];     // 36 KB
    __shared__ float wsh[16*16*9];    //  9 KB
    const int bid = blockIdx.x;
    const int i = bid >> 5, b = (bid >> 4) & 1, k = bid & 15;
    const int tid = threadIdx.x;

    const float* xsrc = x + (b*C + k*16)*HW;            // 16 contiguous channels
    for (int idx = tid; idx < 16*HW; idx += 192) tile[idx] = xsrc[idx];
    const float* wsrc = W1 + (i*C + k*16)*144;          // 2304 contiguous floats
    for (int idx = tid; idx < 2304; idx += 192) wsh[idx] = wsrc[idx];
    __syncthreads();

    float acc[3][16];
    #pragma unroll
    for (int j = 0; j < 3; j++)
        #pragma unroll
        for (int o = 0; o < 16; o++) acc[j][o] = 0.f;

    int p[3], py[3], px[3];
    #pragma unroll
    for (int j = 0; j < 3; j++) {
        p[j] = tid + j*192;          // all < 576
        py[j] = p[j] / 24; px[j] = p[j] % 24;
    }

    for (int cin = 0; cin < 16; cin++) {
        const float* tc = tile + cin*HW;
        #pragma unroll
        for (int dy = 0; dy < 3; dy++) {
            #pragma unroll
            for (int dx = 0; dx < 3; dx++) {
                float xv[3];
                #pragma unroll
                for (int j = 0; j < 3; j++) {
                    int iy = py[j] + dy - 1, ix = px[j] + dx - 1;
                    bool ok = ((unsigned)iy < 24u) && ((unsigned)ix < 24u);
                    xv[j] = ok ? tc[iy*24 + ix] : 0.f;
                }
                const int tap = dy*3 + dx;
                #pragma unroll
                for (int o = 0; o < 16; o++) {
                    float wv = wsh[(o*16 + cin)*9 + tap];   // warp-uniform (broadcast)
                    #pragma unroll
                    for (int j = 0; j < 3; j++)
                        acc[j][o] = fmaf(xv[j], wv, acc[j][o]);
                }
            }
        }
    }

    float* dst = g_h1 + ((i*Bsz + b)*C + k*16)*HW;
    #pragma unroll
    for (int o = 0; o < 16; o++) {
        const int pi = i*C + k*16 + o;
        const float s  = g1[pi] * rsqrtf(v1[pi] + EPSI);
        const float mm = m1[pi], bb = b1[pi];
        #pragma unroll
        for (int j = 0; j < 3; j++) {
            float y = fmaxf(fmaf(acc[j][o] - mm, s, bb), 0.f);
            dst[o*HW + p[j]] = y;
        }
    }
}

// ---------------------------------------------------------------------------
// Kernel 2: fused 1x1 grouped conv (pad=1!) + BN + ReLU + 26x26 spatial mean.
// Never materializes the 541MB `a` tensor. Border pixels of the padded conv
// output are exactly relu(b - m*scale), 100 of them per channel.
// Block = (i, b, group k): h1 tile 16ch x 576 in smem; each warp processes
// 4 output channels at once (weights in registers -> 0.25 LDS/FMA).
// ---------------------------------------------------------------------------
__global__ __launch_bounds__(256) void conv2_pool_kernel(
    const float* __restrict__ W2, const float* __restrict__ g2,
    const float* __restrict__ b2, const float* __restrict__ m2,
    const float* __restrict__ v2)
{
    __shared__ float tile[16*HW];     // 36 KB
    const int bid = blockIdx.x;
    const int i = bid >> 5, b = (bid >> 4) & 1, k = bid & 15;
    const int tid = threadIdx.x, lane = tid & 31, warp = tid >> 5;

    const float* src = g_h1 + ((i*Bsz + b)*C + k*16)*HW;  // contiguous 9216 floats
    for (int idx = tid; idx < 16*HW; idx += 256) tile[idx] = src[idx];
    __syncthreads();

    float* pooled = g_pooled + (i*Bsz + b)*AC + k*400;

    for (int cb = warp*4; cb < 400; cb += 32) {
        float w[4][16], s[4], mm[4], bb[4];
        #pragma unroll
        for (int j = 0; j < 4; j++) {
            const int pi = i*AC + k*400 + cb + j;
            const float* wp = W2 + pi*16;
            #pragma unroll
            for (int cin = 0; cin < 16; cin++) w[j][cin] = wp[cin];
            s[j]  = g2[pi] * rsqrtf(v2[pi] + EPSI);
            mm[j] = m2[pi]; bb[j] = b2[pi];
        }
        float acc[4] = {0.f, 0.f, 0.f, 0.f};
        #pragma unroll 2
        for (int p2 = lane; p2 < HW; p2 += 32) {   // 576 = 18*32, exact
            float d[4] = {0.f, 0.f, 0.f, 0.f};
            #pragma unroll
            for (int cin = 0; cin < 16; cin++) {
                float xv = tile[cin*HW + p2];      // conflict-free (stride-1 lanes)
                #pragma unroll
                for (int j = 0; j < 4; j++) d[j] = fmaf(xv, w[j][cin], d[j]);
            }
            #pragma unroll
            for (int j = 0; j < 4; j++)
                acc[j] += fmaxf(fmaf(d[j] - mm[j], s[j], bb[j]), 0.f);
        }
        #pragma unroll
        for (int j = 0; j < 4; j++) {
            float a = acc[j];
            #pragma unroll
            for (int off = 16; off; off >>= 1)
                a += __shfl_xor_sync(0xffffffffu, a, off);
            if (lane == 0) {
                // 100 border pixels of the (pad=1) 26x26 conv output
                float border = 100.f * fmaxf(fmaf(-mm[j], s[j], bb[j]), 0.f);
                pooled[cb + j] = (a + border) * (1.f / 676.f);
            }
        }
    }
}

// ---------------------------------------------------------------------------
// Kernel 3: affinity row  aff_i[i,b,l] = <pooled[i,b,i*400:..], pooled[i,b,l*400:..]>/16
// ---------------------------------------------------------------------------
__global__ void aff_kernel()
{
    const int t = threadIdx.x;              // 512 threads, one per (i,b,l)
    const int i = t >> 5, b = (t >> 4) & 1, l = t & 15;
    const float* base = g_pooled + (i*Bsz + b)*AC;
    const float* pa = base + i*400;
    const float* pb = base + l*400;
    float s = 0.f;
    #pragma unroll 4
    for (int m3 = 0; m3 < 400; m3++) s = fmaf(pa[m3], pb[m3], s);
    g_aff[(i*Bsz + b)*G + l] = s * (1.f / 16.f);
}

// ---------------------------------------------------------------------------
// Kernel 4: z[i,p,q,cg,hw] = sum_k aff_i[i,p,k] * h1[i,q,k*16+cg,hw]
// output layout (B=2, 512, 24, 24), channel = i*32 + q*16 + cg
// ---------------------------------------------------------------------------
__global__ __launch_bounds__(256) void out_kernel(float* __restrict__ out)
{
    const int idx = blockIdx.x*256 + threadIdx.x;
    if (idx >= Bsz*512*HW) return;
    const int pix = idx % HW;
    const int ch  = (idx / HW) & 511;
    const int p   = idx / (512*HW);
    const int i = ch >> 5, q = (ch >> 4) & 1, cg = ch & 15;

    const float* a = g_aff + (i*Bsz + p)*G;             // warp-uniform
    const float* h = g_h1 + ((i*Bsz + q)*C + cg)*HW + pix;  // coalesced over pix
    float s = 0.f;
    #pragma unroll
    for (int kk = 0; kk < 16; kk++)
        s = fmaf(a[kk], h[kk*16*HW], s);
    out[idx] = s;
}

// ---------------------------------------------------------------------------
extern "C" void kernel_launch(void* const* d_in, const int* in_sizes, int n_in,
                              void* d_out, int out_size)
{
    const float* x  = (const float*)d_in[0];
    const float* W1 = (const float*)d_in[1];
    const float* g1 = (const float*)d_in[2];
    const float* b1 = (const float*)d_in[3];
    const float* m1 = (const float*)d_in[4];
    const float* v1 = (const float*)d_in[5];
    const float* W2 = (const float*)d_in[6];
    const float* g2 = (const float*)d_in[7];
    const float* b2 = (const float*)d_in[8];
    const float* m2 = (const float*)d_in[9];
    const float* v2 = (const float*)d_in[10];
    float* out = (float*)d_out;

    conv1_kernel<<<512, 192>>>(x, W1, g1, b1, m1, v1);
    conv2_pool_kernel<<<512, 256>>>(W2, g2, b2, m2, v2);
    aff_kernel<<<1, 512>>>();
    out_kernel<<<(Bsz*512*HW + 255)/256, 256>>>(out);
}

// round 3
// speedup vs baseline: 1.7774x; 1.7774x over previous
#include <cuda_runtime.h>

#define G   16
#define Bsz 2
#define C   256
#define Cg  16
#define HW  576     // 24*24
#define AC  6400    // 25*C
#define EPSI 1e-5f

typedef unsigned long long ull;

// Scratch (device globals — no allocation allowed)
__device__ float g_h1[G*Bsz*C*HW];     // (i,b,c,hw)  18.9 MB
__device__ float g_pooled[G*Bsz*AC];   // (i,b,ac)
__device__ float g_aff[G*Bsz*G];       // aff_i[i,b,l]

// ---- packed f32x2 helpers (sm_103a FFMA2 path, not emitted by ptxas from C++) ----
__device__ __forceinline__ ull pack2(float lo, float hi) {
    ull r; asm("mov.b64 %0, {%1,%2};" : "=l"(r) : "f"(lo), "f"(hi)); return r;
}
__device__ __forceinline__ void unpack2(ull v, float& lo, float& hi) {
    asm("mov.b64 {%0,%1}, %2;" : "=f"(lo), "=f"(hi) : "l"(v));
}
__device__ __forceinline__ ull fma2(ull a, ull b, ull c) {
    ull d; asm("fma.rn.f32x2 %0, %1, %2, %3;" : "=l"(d) : "l"(a), "l"(b), "l"(c));
    return d;
}

// ---------------------------------------------------------------------------
// Kernel 1: 16x grouped 3x3 conv + BN + ReLU  ->  g_h1
// Block = (i, b, group k). 192 threads, each owns 3 pixels x 16 out-channels.
// Weights transposed in smem to [cin][tap][o] so one broadcast LDS.64 yields
// an output-channel pair -> FFMA2 over o-pairs (24 FFMA2 replace 48 FFMA).
// ---------------------------------------------------------------------------
__global__ __launch_bounds__(192) void conv1_kernel(
    const float* __restrict__ x,  const float* __restrict__ W1,
    const float* __restrict__ g1, const float* __restrict__ b1,
    const float* __restrict__ m1, const float* __restrict__ v1)
{
    __shared__ float tile[16*HW];             // 36 KB
    __shared__ __align__(8) float wsh[144*16];// 9 KB, layout [(cin*9+tap)*16 + o]
    const int bid = blockIdx.x;
    const int i = bid >> 5, b = (bid >> 4) & 1, k = bid & 15;
    const int tid = threadIdx.x;

    const float* xsrc = x + (b*C + k*16)*HW;            // 16 contiguous channels
    for (int idx = tid; idx < 16*HW; idx += 192) tile[idx] = xsrc[idx];
    const float* wsrc = W1 + (i*C + k*16)*144;          // 2304 contiguous floats
    for (int idx = tid; idx < 2304; idx += 192) {
        int o = idx / 144, r = idx % 144;               // r = cin*9 + tap
        wsh[r*16 + o] = wsrc[idx];
    }
    __syncthreads();

    ull acc2[3][8];
    #pragma unroll
    for (int j = 0; j < 3; j++)
        #pragma unroll
        for (int op = 0; op < 8; op++) acc2[j][op] = 0ull;

    int p[3], py[3], px[3];
    #pragma unroll
    for (int j = 0; j < 3; j++) {
        p[j] = tid + j*192;          // all < 576
        py[j] = p[j] / 24; px[j] = p[j] % 24;
    }

    for (int cin = 0; cin < 16; cin++) {
        const float* tc = tile + cin*HW;
        #pragma unroll
        for (int dy = 0; dy < 3; dy++) {
            #pragma unroll
            for (int dx = 0; dx < 3; dx++) {
                ull xp[3];
                #pragma unroll
                for (int j = 0; j < 3; j++) {
                    int iy = py[j] + dy - 1, ix = px[j] + dx - 1;
                    bool ok = ((unsigned)iy < 24u) && ((unsigned)ix < 24u);
                    float xv = ok ? tc[iy*24 + ix] : 0.f;
                    xp[j] = pack2(xv, xv);
                }
                const ull* wrow = (const ull*)&wsh[(cin*9 + dy*3 + dx)*16];
                #pragma unroll
                for (int op = 0; op < 8; op++) {
                    ull wv = wrow[op];                  // broadcast LDS.64
                    #pragma unroll
                    for (int j = 0; j < 3; j++)
                        acc2[j][op] = fma2(xp[j], wv, acc2[j][op]);
                }
            }
        }
    }

    float* dst = g_h1 + ((i*Bsz + b)*C + k*16)*HW;
    #pragma unroll
    for (int op = 0; op < 8; op++) {
        float a0[3], a1[3];
        #pragma unroll
        for (int j = 0; j < 3; j++) unpack2(acc2[j][op], a0[j], a1[j]);
        #pragma unroll
        for (int half = 0; half < 2; half++) {
            const int o = op*2 + half;
            const int pi = i*C + k*16 + o;
            const float s  = g1[pi] * rsqrtf(v1[pi] + EPSI);
            const float mm = m1[pi], bb = b1[pi];
            #pragma unroll
            for (int j = 0; j < 3; j++) {
                float av = half ? a1[j] : a0[j];
                dst[o*HW + p[j]] = fmaxf(fmaf(av - mm, s, bb), 0.f);
            }
        }
    }
}

// ---------------------------------------------------------------------------
// Kernel 2: fused 1x1 grouped conv (pad=1!) + BN + ReLU + 26x26 spatial mean.
// Never materializes the 541MB `a` tensor. Each lane owns a PIXEL PAIR
// (LDS.64) against 4 output channels whose weights sit pre-packed (w,w) in
// registers -> 64 FFMA2 per 16 LDS.64 per iter = 128 MACs, crossbar and
// fma-pipe co-binding. 128 threads/block to keep 2+ blocks/SM despite regs.
// ---------------------------------------------------------------------------
__global__ __launch_bounds__(128) void conv2_pool_kernel(
    const float* __restrict__ W2, const float* __restrict__ g2,
    const float* __restrict__ b2, const float* __restrict__ m2,
    const float* __restrict__ v2)
{
    __shared__ __align__(8) float tile[16*HW];     // 36 KB
    const int bid = blockIdx.x;
    const int i = bid >> 5, b = (bid >> 4) & 1, k = bid & 15;
    const int tid = threadIdx.x, lane = tid & 31, warp = tid >> 5;

    const float* src = g_h1 + ((i*Bsz + b)*C + k*16)*HW;  // contiguous 9216 floats
    for (int idx = tid; idx < 16*HW; idx += 128) tile[idx] = src[idx];
    __syncthreads();

    float* pooled = g_pooled + (i*Bsz + b)*AC + k*400;

    for (int cb = warp*4; cb < 400; cb += 16) {           // 25 cb-blocks per warp
        ull w2[4][16], s2[4], c2[4];
        float sj[4], cj[4];
        #pragma unroll
        for (int j = 0; j < 4; j++) {
            const int pi = i*AC + k*400 + cb + j;
            const float* wp = W2 + pi*16;
            #pragma unroll
            for (int cin = 0; cin < 16; cin++) {
                float wv = wp[cin];
                w2[j][cin] = pack2(wv, wv);
            }
            float sc = g2[pi] * rsqrtf(v2[pi] + EPSI);
            float cc = fmaf(-m2[pi], sc, b2[pi]);          // b - m*s
            sj[j] = sc; cj[j] = cc;
            s2[j] = pack2(sc, sc);
            c2[j] = pack2(cc, cc);
        }

        float acc[4] = {0.f, 0.f, 0.f, 0.f};
        #pragma unroll 3
        for (int it = 0; it < 9; it++) {                   // 288 pairs / 32 lanes
            const int pp2 = (lane + it*32) * 2;
            ull d2[4] = {0ull, 0ull, 0ull, 0ull};
            #pragma unroll
            for (int cin = 0; cin < 16; cin++) {
                ull xv = *(const ull*)&tile[cin*HW + pp2]; // LDS.64, conflict-free
                #pragma unroll
                for (int j = 0; j < 4; j++)
                    d2[j] = fma2(xv, w2[j][cin], d2[j]);
            }
            #pragma unroll
            for (int j = 0; j < 4; j++) {
                ull t = fma2(d2[j], s2[j], c2[j]);         // BN, both pixels
                float lo, hi; unpack2(t, lo, hi);
                acc[j] += fmaxf(lo, 0.f) + fmaxf(hi, 0.f); // ReLU + pool accum
            }
        }
        #pragma unroll
        for (int j = 0; j < 4; j++) {
            float a = acc[j];
            #pragma unroll
            for (int off = 16; off; off >>= 1)
                a += __shfl_xor_sync(0xffffffffu, a, off);
            if (lane == 0) {
                // 100 border pixels of the (pad=1) 26x26 conv output
                float border = 100.f * fmaxf(cj[j], 0.f);
                pooled[cb + j] = (a + border) * (1.f / 676.f);
            }
        }
    }
}

// ---------------------------------------------------------------------------
// Kernel 3: aff_i[i,b,l] = <pooled[i,b,i*400:..], pooled[i,b,l*400:..]>/16
// One warp per (i,b,l): 512 warps, latency-hidden strided loads + shfl reduce.
// ---------------------------------------------------------------------------
__global__ __launch_bounds__(256) void aff_kernel()
{
    const int gw = blockIdx.x*8 + (threadIdx.x >> 5);   // 0..511
    const int lane = threadIdx.x & 31;
    const int i = gw >> 5, b = (gw >> 4) & 1, l = gw & 15;
    const float* base = g_pooled + (i*Bsz + b)*AC;
    const float* pa = base + i*400;
    const float* pb = base + l*400;
    float s = 0.f;
    #pragma unroll
    for (int m3 = lane; m3 < 400; m3 += 32)
        s = fmaf(pa[m3], pb[m3], s);
    #pragma unroll
    for (int off = 16; off; off >>= 1)
        s += __shfl_xor_sync(0xffffffffu, s, off);
    if (lane == 0) g_aff[(i*Bsz + b)*G + l] = s * (1.f / 16.f);
}

// ---------------------------------------------------------------------------
// Kernel 4: z[i,p,q,cg,hw] = sum_k aff_i[i,p,k] * h1[i,q,k*16+cg,hw]
// Each thread produces BOTH p outputs from one set of h1 loads (halves reads).
// ---------------------------------------------------------------------------
__global__ __launch_bounds__(256) void out_kernel(float* __restrict__ out)
{
    const int idx = blockIdx.x*256 + threadIdx.x;
    if (idx >= 512*HW) return;
    const int pix = idx % HW;
    const int ch  = idx / HW;                 // 0..511
    const int i = ch >> 5, q = (ch >> 4) & 1, cg = ch & 15;

    const float* a0 = g_aff + (i*Bsz + 0)*G;              // warp-uniform
    const float* a1 = g_aff + (i*Bsz + 1)*G;
    const float* h  = g_h1 + ((i*Bsz + q)*C + cg)*HW + pix;  // coalesced over pix
    float s0 = 0.f, s1 = 0.f;
    #pragma unroll
    for (int kk = 0; kk < 16; kk++) {
        float hv = h[kk*16*HW];
        s0 = fmaf(a0[kk], hv, s0);
        s1 = fmaf(a1[kk], hv, s1);
    }
    out[ch*HW + pix]            = s0;   // p = 0
    out[512*HW + ch*HW + pix]   = s1;   // p = 1
}

// ---------------------------------------------------------------------------
extern "C" void kernel_launch(void* const* d_in, const int* in_sizes, int n_in,
                              void* d_out, int out_size)
{
    const float* x  = (const float*)d_in[0];
    const float* W1 = (const float*)d_in[1];
    const float* g1 = (const float*)d_in[2];
    const float* b1 = (const float*)d_in[3];
    const float* m1 = (const float*)d_in[4];
    const float* v1 = (const float*)d_in[5];
    const float* W2 = (const float*)d_in[6];
    const float* g2 = (const float*)d_in[7];
    const float* b2 = (const float*)d_in[8];
    const float* m2 = (const float*)d_in[9];
    const float* v2 = (const float*)d_in[10];
    float* out = (float*)d_out;

    conv1_kernel<<<512, 192>>>(x, W1, g1, b1, m1, v1);
    conv2_pool_kernel<<<512, 128>>>(W2, g2, b2, m2, v2);
    aff_kernel<<<64, 256>>>();
    out_kernel<<<(512*HW + 255)/256, 256>>>(out);
}